// round 5
// baseline (speedup 1.0000x reference)
#include <cuda_runtime.h>
#include <cuda_bf16.h>

// ---------------------------------------------------------------------------
// BipartiteGATConv — round 5: CSR gather aggregation (no output atomics,
// no separate denominator pass).
//   feat + alpha_src : fused src GEMM
//   out  + alpha_dst : fused dst GEMM (self term written to out)
//   hist/scan/scatter: build CSR (edge ids bucketed by dst) + per-edge weights
//   aggr             : warp per dst; gather feat, local softmax denom, RMW out
// Softmax max-subtraction skipped (shift-invariant; alphas are tiny).
// ---------------------------------------------------------------------------

#define MAX_N   50000
#define MAX_E   800000
#define FDIM    128
#define HEADS   4

__device__ __align__(16) float g_feat[MAX_N * FDIM];
__device__ __align__(16) float g_asrc[MAX_N * HEADS];
__device__ __align__(16) float g_adst[MAX_N * HEADS];
__device__ __align__(16) float g_fold_v[FDIM * HEADS];
__device__ int   g_deg[MAX_N];
__device__ int   g_row[MAX_N + 1];
__device__ int   g_cursor[MAX_N];
__device__ int   g_csr_s[MAX_E];
__device__ __align__(16) float g_csr_w[MAX_E * HEADS];

__device__ __forceinline__ float leaky02(float z) {
    return z > 0.f ? z : 0.2f * z;
}

// ---------------- fold: v[k,h] = sum_d W_dst[k, h*32+d] * att_dst[h*32+d]
__global__ void fold_kernel(const float* __restrict__ W_dst,
                            const float* __restrict__ att_dst) {
    int k = threadIdx.x;   // 128 threads
    #pragma unroll
    for (int h = 0; h < HEADS; h++) {
        float s = 0.f;
        #pragma unroll 8
        for (int d = 0; d < 32; d++)
            s += W_dst[k * FDIM + h * 32 + d] * att_dst[h * 32 + d];
        g_fold_v[k * HEADS + h] = s;
    }
}

// ---------------- CSR build ----------------
__global__ void zero_deg_kernel(int n) {
    int i = blockIdx.x * blockDim.x + threadIdx.x;
    if (i < n) g_deg[i] = 0;
}

__global__ void hist_kernel(const int* __restrict__ ed, int E) {
    int e = blockIdx.x * blockDim.x + threadIdx.x;
    if (e < E) atomicAdd(&g_deg[ed[e]], 1);
}

// single-block exclusive scan of g_deg[0..n) -> g_row, g_cursor
__global__ __launch_bounds__(1024)
void scan_kernel(int n) {
    __shared__ int ssum[1024];
    int t = threadIdx.x;
    int chunk = (n + 1023) >> 10;
    int lo = t * chunk;
    int hi = lo + chunk; if (hi > n) hi = n;

    int s = 0;
    for (int i = lo; i < hi; i++) s += g_deg[i];
    ssum[t] = s;
    __syncthreads();
    // Hillis-Steele inclusive scan
    for (int off = 1; off < 1024; off <<= 1) {
        int v = (t >= off) ? ssum[t - off] : 0;
        __syncthreads();
        ssum[t] += v;
        __syncthreads();
    }
    int run = (t > 0) ? ssum[t - 1] : 0;   // exclusive prefix of this chunk
    for (int i = lo; i < hi; i++) {
        g_row[i] = run;
        g_cursor[i] = run;
        run += g_deg[i];
    }
    if (lo < n && hi == n) g_row[n] = run;
}

// ---------------- scatter: bucket edges by dst, compute per-head weights
__global__ void scatter_kernel(const int* __restrict__ es,
                               const int* __restrict__ ed, int E) {
    int e = blockIdx.x * blockDim.x + threadIdx.x;
    if (e >= E) return;
    int s = es[e], d = ed[e];
    const float4 as = ((const float4*)g_asrc)[s];
    const float4 ad = ((const float4*)g_adst)[d];
    float4 w;
    w.x = __expf(leaky02(as.x + ad.x));
    w.y = __expf(leaky02(as.y + ad.y));
    w.z = __expf(leaky02(as.z + ad.z));
    w.w = __expf(leaky02(as.w + ad.w));
    int pos = atomicAdd(&g_cursor[d], 1);
    g_csr_s[pos] = s;
    ((float4*)g_csr_w)[pos] = w;
}

// ---------------- aggregate: one warp per dst, no atomics
__global__ __launch_bounds__(256)
void aggr_kernel(float* __restrict__ out, int n_dst) {
    int d = (blockIdx.x * blockDim.x + threadIdx.x) >> 5;
    int lane = threadIdx.x & 31;
    if (d >= n_dst) return;
    int h = lane >> 3;

    int i   = g_row[d];
    int end = g_row[d + 1];

    float4 acc = make_float4(0.f, 0.f, 0.f, 0.f);
    float wsum = 0.f;
    const float4* feat4 = (const float4*)g_feat;
    const float4* csrw4 = (const float4*)g_csr_w;

    // software-pipelined: prefetch next edge's index/weight
    int   s_cur = (i < end) ? g_csr_s[i] : 0;
    float4 w_cur = (i < end) ? csrw4[i] : make_float4(0.f, 0.f, 0.f, 0.f);
    for (; i < end; ) {
        int inext = i + 1;
        int   s_nxt = 0;
        float4 w_nxt = make_float4(0.f, 0.f, 0.f, 0.f);
        if (inext < end) { s_nxt = g_csr_s[inext]; w_nxt = csrw4[inext]; }
        float w = (h < 2) ? ((h == 0) ? w_cur.x : w_cur.y)
                          : ((h == 2) ? w_cur.z : w_cur.w);
        float4 f = feat4[s_cur * 32 + lane];
        acc.x += w * f.x; acc.y += w * f.y;
        acc.z += w * f.z; acc.w += w * f.w;
        wsum += w;
        s_cur = s_nxt; w_cur = w_nxt;
        i = inext;
    }

    float rs = 1.f / (wsum + 1e-16f);
    float4* out4 = (float4*)out;
    float4 o = out4[d * 32 + lane];   // self term from dst GEMM
    o.x += acc.x * rs; o.y += acc.y * rs;
    o.z += acc.z * rs; o.w += acc.w * rs;
    out4[d * 32 + lane] = o;
}

// ---------------- tiled GEMM: 128-wide, BM=128, BK=16, TM=TN=8
#define BM 128
#define BN 128
#define BK 16
#define TM 8
#define TN 8

// MODE 0: feat GEMM + alpha_src epilogue (att in smem)
// MODE 1: out GEMM + bias + alpha_dst in mainloop (fold_v in smem)
template <int MODE>
__global__ __launch_bounds__(256, 2)
void gemm128_kernel(const float* __restrict__ A,
                    const float* __restrict__ B,
                    const float* __restrict__ aux,   // att_src (M0) / bias (M1)
                    float* __restrict__ C,
                    float* __restrict__ alpha_out,
                    int nrows) {
    __shared__ float As[2][BK][BM];
    __shared__ float Bs[2][BK][BN];
    __shared__ float xtra[MODE == 0 ? FDIM : FDIM * HEADS];

    int tid = threadIdx.x;
    int tn_idx = tid & 15;
    int tm_idx = tid >> 4;
    int tm0 = tm_idx * TM;
    int tn0 = tn_idx * TN;
    int m0 = blockIdx.x * BM;

    if (MODE == 0) {
        if (tid < FDIM) xtra[tid] = aux[tid];   // att_src, layout [h*32+d]
    } else {
        xtra[tid] = g_fold_v[tid];
        xtra[tid + 256] = g_fold_v[tid + 256];
    }

    float acc[TM][TN];
    #pragma unroll
    for (int i = 0; i < TM; i++)
        #pragma unroll
        for (int j = 0; j < TN; j++) acc[i][j] = 0.f;

    int af_row[2], af_k4[2];
    int bf_k[2], bf_n4[2];
    #pragma unroll
    for (int i = 0; i < 2; i++) {
        int f = tid + i * 256;
        af_row[i] = f >> 2;
        af_k4[i]  = (f & 3) * 4;
        bf_k[i]   = f >> 5;
        bf_n4[i]  = (f & 31) * 4;
    }

    float4 a_reg[2], b_reg[2];
    const float4 zero4 = make_float4(0.f, 0.f, 0.f, 0.f);

    #pragma unroll
    for (int i = 0; i < 2; i++) {
        int grow = m0 + af_row[i];
        a_reg[i] = (grow < nrows)
            ? *(const float4*)(A + (size_t)grow * FDIM + af_k4[i]) : zero4;
        b_reg[i] = *(const float4*)(B + (size_t)bf_k[i] * FDIM + bf_n4[i]);
    }
    #pragma unroll
    for (int i = 0; i < 2; i++) {
        As[0][af_k4[i] + 0][af_row[i]] = a_reg[i].x;
        As[0][af_k4[i] + 1][af_row[i]] = a_reg[i].y;
        As[0][af_k4[i] + 2][af_row[i]] = a_reg[i].z;
        As[0][af_k4[i] + 3][af_row[i]] = a_reg[i].w;
        *(float4*)&Bs[0][bf_k[i]][bf_n4[i]] = b_reg[i];
    }
    __syncthreads();

    // alpha_dst partition (MODE 1): head h, 2 rows starting at tm0+qq
    int h  = tn_idx >> 2;
    int qq = (tn_idx & 3) * 2;
    float av0 = 0.f, av1 = 0.f;

    int buf = 0;
    const int NT = FDIM / BK;  // 8 tiles
    for (int t = 0; t < NT; t++) {
        if (t + 1 < NT) {
            int kt = (t + 1) * BK;
            #pragma unroll
            for (int i = 0; i < 2; i++) {
                int grow = m0 + af_row[i];
                a_reg[i] = (grow < nrows)
                    ? *(const float4*)(A + (size_t)grow * FDIM + kt + af_k4[i]) : zero4;
                b_reg[i] = *(const float4*)(B + (size_t)(kt + bf_k[i]) * FDIM + bf_n4[i]);
            }
        }

        #pragma unroll
        for (int k = 0; k < BK; k++) {
            float4 a0 = *(const float4*)&As[buf][k][tm0];
            float4 a1 = *(const float4*)&As[buf][k][tm0 + 4];
            float4 b0 = *(const float4*)&Bs[buf][k][tn0];
            float4 b1 = *(const float4*)&Bs[buf][k][tn0 + 4];
            float avv[TM] = {a0.x, a0.y, a0.z, a0.w, a1.x, a1.y, a1.z, a1.w};
            float bvv[TN] = {b0.x, b0.y, b0.z, b0.w, b1.x, b1.y, b1.z, b1.w};
            #pragma unroll
            for (int i = 0; i < TM; i++)
                #pragma unroll
                for (int j = 0; j < TN; j++)
                    acc[i][j] += avv[i] * bvv[j];
            if (MODE == 1) {
                float vv = xtra[(t * BK + k) * HEADS + h];
                av0 += As[buf][k][tm0 + qq]     * vv;
                av1 += As[buf][k][tm0 + qq + 1] * vv;
            }
        }

        if (t + 1 < NT) {
            int nb = buf ^ 1;
            #pragma unroll
            for (int i = 0; i < 2; i++) {
                As[nb][af_k4[i] + 0][af_row[i]] = a_reg[i].x;
                As[nb][af_k4[i] + 1][af_row[i]] = a_reg[i].y;
                As[nb][af_k4[i] + 2][af_row[i]] = a_reg[i].z;
                As[nb][af_k4[i] + 3][af_row[i]] = a_reg[i].w;
                *(float4*)&Bs[nb][bf_k[i]][bf_n4[i]] = b_reg[i];
            }
            __syncthreads();
            buf = nb;
        }
    }

    // epilogue: bias (MODE 1)
    float4 bb0 = zero4, bb1 = zero4;
    if (MODE == 1) {
        bb0 = *(const float4*)(aux + tn0);
        bb1 = *(const float4*)(aux + tn0 + 4);
    }
    #pragma unroll
    for (int i = 0; i < TM; i++) {
        int row = m0 + tm0 + i;
        if (row < nrows) {
            float4 o0 = make_float4(acc[i][0] + bb0.x, acc[i][1] + bb0.y,
                                    acc[i][2] + bb0.z, acc[i][3] + bb0.w);
            float4 o1 = make_float4(acc[i][4] + bb1.x, acc[i][5] + bb1.y,
                                    acc[i][6] + bb1.z, acc[i][7] + bb1.w);
            *(float4*)(C + (size_t)row * FDIM + tn0)     = o0;
            *(float4*)(C + (size_t)row * FDIM + tn0 + 4) = o1;
        }
    }

    if (MODE == 0) {
        float a_att[TN];
        #pragma unroll
        for (int j = 0; j < TN; j++) a_att[j] = xtra[tn0 + j];
        #pragma unroll
        for (int i = 0; i < TM; i++) {
            float p = 0.f;
            #pragma unroll
            for (int j = 0; j < TN; j++) p += acc[i][j] * a_att[j];
            p += __shfl_xor_sync(0xffffffffu, p, 1);
            p += __shfl_xor_sync(0xffffffffu, p, 2);
            if ((tn_idx & 3) == 0) {
                int row = m0 + tm0 + i;
                if (row < nrows) alpha_out[row * HEADS + h] = p;
            }
        }
    } else {
        int r0 = m0 + tm0 + qq;
        if (r0 < nrows)     alpha_out[r0 * HEADS + h]       = av0;
        if (r0 + 1 < nrows) alpha_out[(r0 + 1) * HEADS + h] = av1;
    }
}

// ---------------------------------------------------------------------------
extern "C" void kernel_launch(void* const* d_in, const int* in_sizes, int n_in,
                              void* d_out, int out_size) {
    const float* x_src    = (const float*)d_in[0];
    const float* x_dst    = (const float*)d_in[1];
    const int*   edge_src = (const int*)d_in[2];
    const int*   edge_dst = (const int*)d_in[3];
    int off = (n_in >= 11) ? 5 : 4;  // skip scalar num_dst if present
    const float* W_src   = (const float*)d_in[off + 0];
    const float* W_dst   = (const float*)d_in[off + 1];
    const float* att_src = (const float*)d_in[off + 2];
    const float* att_dst = (const float*)d_in[off + 3];
    const float* W_self  = (const float*)d_in[off + 4];
    const float* b_self  = (const float*)d_in[off + 5];
    float* out = (float*)d_out;

    int n_src = in_sizes[0] / FDIM;
    int n_dst = in_sizes[1] / FDIM;
    int E     = in_sizes[2];

    static float* p_feat = nullptr;
    static float* p_asrc = nullptr;
    static float* p_adst = nullptr;
    if (!p_feat) {
        cudaGetSymbolAddress((void**)&p_feat, g_feat);
        cudaGetSymbolAddress((void**)&p_asrc, g_asrc);
        cudaGetSymbolAddress((void**)&p_adst, g_adst);
    }

    // 1) fold for alpha_dst
    fold_kernel<<<1, 128>>>(W_dst, att_dst);

    // 2) CSR skeleton (independent of GEMMs)
    zero_deg_kernel<<<(n_dst + 255) / 256, 256>>>(n_dst);
    hist_kernel<<<(E + 255) / 256, 256>>>(edge_dst, E);
    scan_kernel<<<1, 1024>>>(n_dst);

    // 3) fused GEMMs
    gemm128_kernel<0><<<(n_src + BM - 1) / BM, 256>>>(
        x_src, W_src, att_src, p_feat, p_asrc, n_src);
    gemm128_kernel<1><<<(n_dst + BM - 1) / BM, 256>>>(
        x_dst, W_self, b_self, out, p_adst, n_dst);

    // 4) scatter edges into CSR with per-head weights
    scatter_kernel<<<(E + 255) / 256, 256>>>(edge_src, edge_dst, E);

    // 5) gather-aggregate: warp per dst, no atomics
    long long total_threads = (long long)n_dst * 32;
    int blocks = (int)((total_threads + 255) / 256);
    aggr_kernel<<<blocks, 256>>>(out, n_dst);
}

// round 6
// speedup vs baseline: 1.3516x; 1.3516x over previous
#include <cuda_runtime.h>
#include <cuda_bf16.h>

// ---------------------------------------------------------------------------
// BipartiteGATConv — round 6: round-5 CSR design + parallel 3-phase scan
// (round-5's single-block scan was 78.8us on one SM; everything else kept).
// ---------------------------------------------------------------------------

#define MAX_N   50000
#define MAX_E   800000
#define FDIM    128
#define HEADS   4
#define SCAN_TILE 1024          // elems per scan block (256 thr x 4)
#define MAX_SB  ((MAX_N + SCAN_TILE - 1) / SCAN_TILE)

__device__ __align__(16) float g_feat[MAX_N * FDIM];
__device__ __align__(16) float g_asrc[MAX_N * HEADS];
__device__ __align__(16) float g_adst[MAX_N * HEADS];
__device__ __align__(16) float g_fold_v[FDIM * HEADS];
__device__ __align__(16) int   g_deg[MAX_N];
__device__ int   g_row[MAX_N + 1];
__device__ int   g_cursor[MAX_N];
__device__ int   g_bsum[MAX_SB];
__device__ int   g_boff[MAX_SB];
__device__ int   g_csr_s[MAX_E];
__device__ __align__(16) float g_csr_w[MAX_E * HEADS];

__device__ __forceinline__ float leaky02(float z) {
    return z > 0.f ? z : 0.2f * z;
}

// ---------------- fold: v[k,h] = sum_d W_dst[k, h*32+d] * att_dst[h*32+d]
__global__ void fold_kernel(const float* __restrict__ W_dst,
                            const float* __restrict__ att_dst) {
    int k = threadIdx.x;   // 128 threads
    #pragma unroll
    for (int h = 0; h < HEADS; h++) {
        float s = 0.f;
        #pragma unroll 8
        for (int d = 0; d < 32; d++)
            s += W_dst[k * FDIM + h * 32 + d] * att_dst[h * 32 + d];
        g_fold_v[k * HEADS + h] = s;
    }
}

// ---------------- CSR build ----------------
__global__ void zero_deg_kernel(int n) {
    int i = blockIdx.x * blockDim.x + threadIdx.x;
    if (i < n) g_deg[i] = 0;
}

__global__ void hist_kernel(const int* __restrict__ ed, int E) {
    int e = blockIdx.x * blockDim.x + threadIdx.x;
    if (e < E) atomicAdd(&g_deg[ed[e]], 1);
}

// phase 1: per-block local exclusive scan (4 elems/thread), block totals
__global__ __launch_bounds__(256)
void scan_local_kernel(int n) {
    __shared__ int warp_tot[8];
    int t = threadIdx.x;
    int lane = t & 31, w = t >> 5;
    int base = blockIdx.x * SCAN_TILE + t * 4;

    int4 v = make_int4(0, 0, 0, 0);
    if (base + 3 < n) {
        v = *(const int4*)(g_deg + base);
    } else if (base < n) {
        v.x = g_deg[base];
        if (base + 1 < n) v.y = g_deg[base + 1];
        if (base + 2 < n) v.z = g_deg[base + 2];
    }
    int tot = v.x + v.y + v.z + v.w;

    // warp inclusive scan of per-thread totals
    int inc = tot;
    #pragma unroll
    for (int off = 1; off < 32; off <<= 1) {
        int x = __shfl_up_sync(0xffffffffu, inc, off);
        if (lane >= off) inc += x;
    }
    if (lane == 31) warp_tot[w] = inc;
    __syncthreads();
    if (t < 8) {
        int x = warp_tot[t];
        #pragma unroll
        for (int off = 1; off < 8; off <<= 1) {
            int y = __shfl_up_sync(0xffu, x, off);
            if (t >= off) x += y;
        }
        warp_tot[t] = x;    // inclusive warp offsets
    }
    __syncthreads();

    int excl = (w > 0 ? warp_tot[w - 1] : 0) + (inc - tot);
    if (base < n) {
        g_row[base] = excl;
        if (base + 1 < n) g_row[base + 1] = excl + v.x;
        if (base + 2 < n) g_row[base + 2] = excl + v.x + v.y;
        if (base + 3 < n) g_row[base + 3] = excl + v.x + v.y + v.z;
    }
    if (t == 0) g_bsum[blockIdx.x] = warp_tot[7];
}

// phase 2: scan block sums (nb <= 256), write total to g_row[n]
__global__ __launch_bounds__(256)
void scan_bsum_kernel(int nb, int n) {
    __shared__ int s[256];
    int t = threadIdx.x;
    s[t] = (t < nb) ? g_bsum[t] : 0;
    __syncthreads();
    #pragma unroll
    for (int off = 1; off < 256; off <<= 1) {
        int v = (t >= off) ? s[t - off] : 0;
        __syncthreads();
        s[t] += v;
        __syncthreads();
    }
    if (t < nb) g_boff[t] = (t > 0) ? s[t - 1] : 0;
    if (t == 0) g_row[n] = s[255];
}

// phase 3: add block offsets; mirror into cursor
__global__ __launch_bounds__(256)
void scan_apply_kernel(int n) {
    int t = threadIdx.x;
    int base = blockIdx.x * SCAN_TILE + t * 4;
    int off = g_boff[blockIdx.x];
    #pragma unroll
    for (int j = 0; j < 4; j++) {
        int i = base + j;
        if (i < n) {
            int r = g_row[i] + off;
            g_row[i] = r;
            g_cursor[i] = r;
        }
    }
}

// ---------------- scatter: bucket edges by dst, compute per-head weights
__global__ void scatter_kernel(const int* __restrict__ es,
                               const int* __restrict__ ed, int E) {
    int e = blockIdx.x * blockDim.x + threadIdx.x;
    if (e >= E) return;
    int s = es[e], d = ed[e];
    const float4 as = ((const float4*)g_asrc)[s];
    const float4 ad = ((const float4*)g_adst)[d];
    float4 w;
    w.x = __expf(leaky02(as.x + ad.x));
    w.y = __expf(leaky02(as.y + ad.y));
    w.z = __expf(leaky02(as.z + ad.z));
    w.w = __expf(leaky02(as.w + ad.w));
    int pos = atomicAdd(&g_cursor[d], 1);
    g_csr_s[pos] = s;
    ((float4*)g_csr_w)[pos] = w;
}

// ---------------- aggregate: one warp per dst, no atomics
__global__ __launch_bounds__(256)
void aggr_kernel(float* __restrict__ out, int n_dst) {
    int d = (blockIdx.x * blockDim.x + threadIdx.x) >> 5;
    int lane = threadIdx.x & 31;
    if (d >= n_dst) return;
    int h = lane >> 3;

    int i   = g_row[d];
    int end = g_row[d + 1];

    float4 acc = make_float4(0.f, 0.f, 0.f, 0.f);
    float wsum = 0.f;
    const float4* feat4 = (const float4*)g_feat;
    const float4* csrw4 = (const float4*)g_csr_w;

    int   s_cur = (i < end) ? g_csr_s[i] : 0;
    float4 w_cur = (i < end) ? csrw4[i] : make_float4(0.f, 0.f, 0.f, 0.f);
    for (; i < end; ) {
        int inext = i + 1;
        int   s_nxt = 0;
        float4 w_nxt = make_float4(0.f, 0.f, 0.f, 0.f);
        if (inext < end) { s_nxt = g_csr_s[inext]; w_nxt = csrw4[inext]; }
        float w = (h < 2) ? ((h == 0) ? w_cur.x : w_cur.y)
                          : ((h == 2) ? w_cur.z : w_cur.w);
        float4 f = feat4[s_cur * 32 + lane];
        acc.x += w * f.x; acc.y += w * f.y;
        acc.z += w * f.z; acc.w += w * f.w;
        wsum += w;
        s_cur = s_nxt; w_cur = w_nxt;
        i = inext;
    }

    float rs = 1.f / (wsum + 1e-16f);
    float4* out4 = (float4*)out;
    float4 o = out4[d * 32 + lane];   // self term from dst GEMM
    o.x += acc.x * rs; o.y += acc.y * rs;
    o.z += acc.z * rs; o.w += acc.w * rs;
    out4[d * 32 + lane] = o;
}

// ---------------- tiled GEMM: 128-wide, BM=128, BK=16, TM=TN=8
#define BM 128
#define BN 128
#define BK 16
#define TM 8
#define TN 8

template <int MODE>
__global__ __launch_bounds__(256, 2)
void gemm128_kernel(const float* __restrict__ A,
                    const float* __restrict__ B,
                    const float* __restrict__ aux,   // att_src (M0) / bias (M1)
                    float* __restrict__ C,
                    float* __restrict__ alpha_out,
                    int nrows) {
    __shared__ float As[2][BK][BM];
    __shared__ float Bs[2][BK][BN];
    __shared__ float xtra[MODE == 0 ? FDIM : FDIM * HEADS];

    int tid = threadIdx.x;
    int tn_idx = tid & 15;
    int tm_idx = tid >> 4;
    int tm0 = tm_idx * TM;
    int tn0 = tn_idx * TN;
    int m0 = blockIdx.x * BM;

    if (MODE == 0) {
        if (tid < FDIM) xtra[tid] = aux[tid];
    } else {
        xtra[tid] = g_fold_v[tid];
        xtra[tid + 256] = g_fold_v[tid + 256];
    }

    float acc[TM][TN];
    #pragma unroll
    for (int i = 0; i < TM; i++)
        #pragma unroll
        for (int j = 0; j < TN; j++) acc[i][j] = 0.f;

    int af_row[2], af_k4[2];
    int bf_k[2], bf_n4[2];
    #pragma unroll
    for (int i = 0; i < 2; i++) {
        int f = tid + i * 256;
        af_row[i] = f >> 2;
        af_k4[i]  = (f & 3) * 4;
        bf_k[i]   = f >> 5;
        bf_n4[i]  = (f & 31) * 4;
    }

    float4 a_reg[2], b_reg[2];
    const float4 zero4 = make_float4(0.f, 0.f, 0.f, 0.f);

    #pragma unroll
    for (int i = 0; i < 2; i++) {
        int grow = m0 + af_row[i];
        a_reg[i] = (grow < nrows)
            ? *(const float4*)(A + (size_t)grow * FDIM + af_k4[i]) : zero4;
        b_reg[i] = *(const float4*)(B + (size_t)bf_k[i] * FDIM + bf_n4[i]);
    }
    #pragma unroll
    for (int i = 0; i < 2; i++) {
        As[0][af_k4[i] + 0][af_row[i]] = a_reg[i].x;
        As[0][af_k4[i] + 1][af_row[i]] = a_reg[i].y;
        As[0][af_k4[i] + 2][af_row[i]] = a_reg[i].z;
        As[0][af_k4[i] + 3][af_row[i]] = a_reg[i].w;
        *(float4*)&Bs[0][bf_k[i]][bf_n4[i]] = b_reg[i];
    }
    __syncthreads();

    int h  = tn_idx >> 2;
    int qq = (tn_idx & 3) * 2;
    float av0 = 0.f, av1 = 0.f;

    int buf = 0;
    const int NT = FDIM / BK;  // 8 tiles
    for (int t = 0; t < NT; t++) {
        if (t + 1 < NT) {
            int kt = (t + 1) * BK;
            #pragma unroll
            for (int i = 0; i < 2; i++) {
                int grow = m0 + af_row[i];
                a_reg[i] = (grow < nrows)
                    ? *(const float4*)(A + (size_t)grow * FDIM + kt + af_k4[i]) : zero4;
                b_reg[i] = *(const float4*)(B + (size_t)(kt + bf_k[i]) * FDIM + bf_n4[i]);
            }
        }

        #pragma unroll
        for (int k = 0; k < BK; k++) {
            float4 a0 = *(const float4*)&As[buf][k][tm0];
            float4 a1 = *(const float4*)&As[buf][k][tm0 + 4];
            float4 b0 = *(const float4*)&Bs[buf][k][tn0];
            float4 b1 = *(const float4*)&Bs[buf][k][tn0 + 4];
            float avv[TM] = {a0.x, a0.y, a0.z, a0.w, a1.x, a1.y, a1.z, a1.w};
            float bvv[TN] = {b0.x, b0.y, b0.z, b0.w, b1.x, b1.y, b1.z, b1.w};
            #pragma unroll
            for (int i = 0; i < TM; i++)
                #pragma unroll
                for (int j = 0; j < TN; j++)
                    acc[i][j] += avv[i] * bvv[j];
            if (MODE == 1) {
                float vv = xtra[(t * BK + k) * HEADS + h];
                av0 += As[buf][k][tm0 + qq]     * vv;
                av1 += As[buf][k][tm0 + qq + 1] * vv;
            }
        }

        if (t + 1 < NT) {
            int nb = buf ^ 1;
            #pragma unroll
            for (int i = 0; i < 2; i++) {
                As[nb][af_k4[i] + 0][af_row[i]] = a_reg[i].x;
                As[nb][af_k4[i] + 1][af_row[i]] = a_reg[i].y;
                As[nb][af_k4[i] + 2][af_row[i]] = a_reg[i].z;
                As[nb][af_k4[i] + 3][af_row[i]] = a_reg[i].w;
                *(float4*)&Bs[nb][bf_k[i]][bf_n4[i]] = b_reg[i];
            }
            __syncthreads();
            buf = nb;
        }
    }

    float4 bb0 = zero4, bb1 = zero4;
    if (MODE == 1) {
        bb0 = *(const float4*)(aux + tn0);
        bb1 = *(const float4*)(aux + tn0 + 4);
    }
    #pragma unroll
    for (int i = 0; i < TM; i++) {
        int row = m0 + tm0 + i;
        if (row < nrows) {
            float4 o0 = make_float4(acc[i][0] + bb0.x, acc[i][1] + bb0.y,
                                    acc[i][2] + bb0.z, acc[i][3] + bb0.w);
            float4 o1 = make_float4(acc[i][4] + bb1.x, acc[i][5] + bb1.y,
                                    acc[i][6] + bb1.z, acc[i][7] + bb1.w);
            *(float4*)(C + (size_t)row * FDIM + tn0)     = o0;
            *(float4*)(C + (size_t)row * FDIM + tn0 + 4) = o1;
        }
    }

    if (MODE == 0) {
        float a_att[TN];
        #pragma unroll
        for (int j = 0; j < TN; j++) a_att[j] = xtra[tn0 + j];
        #pragma unroll
        for (int i = 0; i < TM; i++) {
            float p = 0.f;
            #pragma unroll
            for (int j = 0; j < TN; j++) p += acc[i][j] * a_att[j];
            p += __shfl_xor_sync(0xffffffffu, p, 1);
            p += __shfl_xor_sync(0xffffffffu, p, 2);
            if ((tn_idx & 3) == 0) {
                int row = m0 + tm0 + i;
                if (row < nrows) alpha_out[row * HEADS + h] = p;
            }
        }
    } else {
        int r0 = m0 + tm0 + qq;
        if (r0 < nrows)     alpha_out[r0 * HEADS + h]       = av0;
        if (r0 + 1 < nrows) alpha_out[(r0 + 1) * HEADS + h] = av1;
    }
}

// ---------------------------------------------------------------------------
extern "C" void kernel_launch(void* const* d_in, const int* in_sizes, int n_in,
                              void* d_out, int out_size) {
    const float* x_src    = (const float*)d_in[0];
    const float* x_dst    = (const float*)d_in[1];
    const int*   edge_src = (const int*)d_in[2];
    const int*   edge_dst = (const int*)d_in[3];
    int off = (n_in >= 11) ? 5 : 4;
    const float* W_src   = (const float*)d_in[off + 0];
    const float* W_dst   = (const float*)d_in[off + 1];
    const float* att_src = (const float*)d_in[off + 2];
    const float* att_dst = (const float*)d_in[off + 3];
    const float* W_self  = (const float*)d_in[off + 4];
    const float* b_self  = (const float*)d_in[off + 5];
    float* out = (float*)d_out;

    int n_src = in_sizes[0] / FDIM;
    int n_dst = in_sizes[1] / FDIM;
    int E     = in_sizes[2];

    static float* p_feat = nullptr;
    static float* p_asrc = nullptr;
    static float* p_adst = nullptr;
    if (!p_feat) {
        cudaGetSymbolAddress((void**)&p_feat, g_feat);
        cudaGetSymbolAddress((void**)&p_asrc, g_asrc);
        cudaGetSymbolAddress((void**)&p_adst, g_adst);
    }

    int nb = (n_dst + SCAN_TILE - 1) / SCAN_TILE;

    // 1) fold for alpha_dst
    fold_kernel<<<1, 128>>>(W_dst, att_dst);

    // 2) CSR skeleton: hist + 3-phase parallel scan
    zero_deg_kernel<<<(n_dst + 255) / 256, 256>>>(n_dst);
    hist_kernel<<<(E + 255) / 256, 256>>>(edge_dst, E);
    scan_local_kernel<<<nb, 256>>>(n_dst);
    scan_bsum_kernel<<<1, 256>>>(nb, n_dst);
    scan_apply_kernel<<<nb, 256>>>(n_dst);

    // 3) fused GEMMs
    gemm128_kernel<0><<<(n_src + BM - 1) / BM, 256>>>(
        x_src, W_src, att_src, p_feat, p_asrc, n_src);
    gemm128_kernel<1><<<(n_dst + BM - 1) / BM, 256>>>(
        x_dst, W_self, b_self, out, p_adst, n_dst);

    // 4) scatter edges into CSR with per-head weights
    scatter_kernel<<<(E + 255) / 256, 256>>>(edge_src, edge_dst, E);

    // 5) gather-aggregate: warp per dst, no atomics
    long long total_threads = (long long)n_dst * 32;
    int blocks = (int)((total_threads + 255) / 256);
    aggr_kernel<<<blocks, 256>>>(out, n_dst);
}

// round 7
// speedup vs baseline: 1.4694x; 1.0872x over previous
#include <cuda_runtime.h>
#include <cuda_bf16.h>

// ---------------------------------------------------------------------------
// BipartiteGATConv — round 7:
//   * GEMM inner loop rewritten with packed fma.rn.f32x2 (FFMA2) — 2x fp32
//     FMA throughput on sm_103a, unreachable from plain C++ (ptxas never fuses).
//   * scatter stores src id only; aggr recomputes exp-weights inline.
// ---------------------------------------------------------------------------

#define MAX_N   50000
#define MAX_E   800000
#define FDIM    128
#define HEADS   4
#define SCAN_TILE 1024
#define MAX_SB  ((MAX_N + SCAN_TILE - 1) / SCAN_TILE)

__device__ __align__(16) float g_feat[MAX_N * FDIM];
__device__ __align__(16) float g_asrc[MAX_N * HEADS];
__device__ __align__(16) float g_adst[MAX_N * HEADS];
__device__ __align__(16) float g_fold_v[FDIM * HEADS];
__device__ __align__(16) int   g_deg[MAX_N];
__device__ int   g_row[MAX_N + 1];
__device__ int   g_cursor[MAX_N];
__device__ int   g_bsum[MAX_SB];
__device__ int   g_boff[MAX_SB];
__device__ int   g_csr_s[MAX_E];

typedef unsigned long long u64;

__device__ __forceinline__ float leaky02(float z) {
    return z > 0.f ? z : 0.2f * z;
}

#define FMA_F32X2(d, a, b, c) \
    asm("fma.rn.f32x2 %0, %1, %2, %3;" : "=l"(d) : "l"(a), "l"(b), "l"(c))
#define PACK_DUP_F32X2(d, s) \
    asm("mov.b64 %0, {%1, %1};" : "=l"(d) : "r"(__float_as_uint(s)))
#define UNPACK_F32X2(lo, hi, in) \
    asm("mov.b64 {%0, %1}, %2;" : "=r"(lo), "=r"(hi) : "l"(in))

// ---------------- fold: v[k,h] = sum_d W_dst[k, h*32+d] * att_dst[h*32+d]
__global__ void fold_kernel(const float* __restrict__ W_dst,
                            const float* __restrict__ att_dst) {
    int k = threadIdx.x;   // 128 threads
    #pragma unroll
    for (int h = 0; h < HEADS; h++) {
        float s = 0.f;
        #pragma unroll 8
        for (int d = 0; d < 32; d++)
            s += W_dst[k * FDIM + h * 32 + d] * att_dst[h * 32 + d];
        g_fold_v[k * HEADS + h] = s;
    }
}

// ---------------- CSR build ----------------
__global__ void zero_deg_kernel(int n) {
    int i = blockIdx.x * blockDim.x + threadIdx.x;
    if (i < n) g_deg[i] = 0;
}

__global__ void hist_kernel(const int* __restrict__ ed, int E) {
    int e = blockIdx.x * blockDim.x + threadIdx.x;
    if (e < E) atomicAdd(&g_deg[ed[e]], 1);
}

__global__ __launch_bounds__(256)
void scan_local_kernel(int n) {
    __shared__ int warp_tot[8];
    int t = threadIdx.x;
    int lane = t & 31, w = t >> 5;
    int base = blockIdx.x * SCAN_TILE + t * 4;

    int4 v = make_int4(0, 0, 0, 0);
    if (base + 3 < n) {
        v = *(const int4*)(g_deg + base);
    } else if (base < n) {
        v.x = g_deg[base];
        if (base + 1 < n) v.y = g_deg[base + 1];
        if (base + 2 < n) v.z = g_deg[base + 2];
    }
    int tot = v.x + v.y + v.z + v.w;

    int inc = tot;
    #pragma unroll
    for (int off = 1; off < 32; off <<= 1) {
        int x = __shfl_up_sync(0xffffffffu, inc, off);
        if (lane >= off) inc += x;
    }
    if (lane == 31) warp_tot[w] = inc;
    __syncthreads();
    if (t < 8) {
        int x = warp_tot[t];
        #pragma unroll
        for (int off = 1; off < 8; off <<= 1) {
            int y = __shfl_up_sync(0xffu, x, off);
            if (t >= off) x += y;
        }
        warp_tot[t] = x;
    }
    __syncthreads();

    int excl = (w > 0 ? warp_tot[w - 1] : 0) + (inc - tot);
    if (base < n) {
        g_row[base] = excl;
        if (base + 1 < n) g_row[base + 1] = excl + v.x;
        if (base + 2 < n) g_row[base + 2] = excl + v.x + v.y;
        if (base + 3 < n) g_row[base + 3] = excl + v.x + v.y + v.z;
    }
    if (t == 0) g_bsum[blockIdx.x] = warp_tot[7];
}

__global__ __launch_bounds__(256)
void scan_bsum_kernel(int nb, int n) {
    __shared__ int s[256];
    int t = threadIdx.x;
    s[t] = (t < nb) ? g_bsum[t] : 0;
    __syncthreads();
    #pragma unroll
    for (int off = 1; off < 256; off <<= 1) {
        int v = (t >= off) ? s[t - off] : 0;
        __syncthreads();
        s[t] += v;
        __syncthreads();
    }
    if (t < nb) g_boff[t] = (t > 0) ? s[t - 1] : 0;
    if (t == 0) g_row[n] = s[255];
}

__global__ __launch_bounds__(256)
void scan_apply_kernel(int n) {
    int t = threadIdx.x;
    int base = blockIdx.x * SCAN_TILE + t * 4;
    int off = g_boff[blockIdx.x];
    #pragma unroll
    for (int j = 0; j < 4; j++) {
        int i = base + j;
        if (i < n) {
            int r = g_row[i] + off;
            g_row[i] = r;
            g_cursor[i] = r;
        }
    }
}

// ---------------- scatter: bucket edge src ids by dst (no weights)
__global__ void scatter_kernel(const int* __restrict__ es,
                               const int* __restrict__ ed, int E) {
    int e = blockIdx.x * blockDim.x + threadIdx.x;
    if (e >= E) return;
    int pos = atomicAdd(&g_cursor[ed[e]], 1);
    g_csr_s[pos] = es[e];
}

// ---------------- aggregate: one warp per dst; weights computed inline
__global__ __launch_bounds__(256)
void aggr_kernel(float* __restrict__ out, int n_dst) {
    int d = (blockIdx.x * blockDim.x + threadIdx.x) >> 5;
    int lane = threadIdx.x & 31;
    if (d >= n_dst) return;
    int h = lane >> 3;

    int i   = g_row[d];
    int end = g_row[d + 1];
    float adv = g_adst[d * HEADS + h];

    float4 acc = make_float4(0.f, 0.f, 0.f, 0.f);
    float wsum = 0.f;
    const float4* feat4 = (const float4*)g_feat;

    int   s_cur = (i < end) ? g_csr_s[i] : 0;
    float a_cur = (i < end) ? g_asrc[s_cur * HEADS + h] : 0.f;
    for (; i < end; ) {
        int inext = i + 1;
        int   s_nxt = 0;
        float a_nxt = 0.f;
        if (inext < end) {
            s_nxt = g_csr_s[inext];
            a_nxt = g_asrc[s_nxt * HEADS + h];
        }
        float w = __expf(leaky02(a_cur + adv));
        float4 f = feat4[s_cur * 32 + lane];
        acc.x += w * f.x; acc.y += w * f.y;
        acc.z += w * f.z; acc.w += w * f.w;
        wsum += w;
        s_cur = s_nxt; a_cur = a_nxt;
        i = inext;
    }

    float rs = 1.f / (wsum + 1e-16f);
    float4* out4 = (float4*)out;
    float4 o = out4[d * 32 + lane];   // self term from dst GEMM
    o.x += acc.x * rs; o.y += acc.y * rs;
    o.z += acc.z * rs; o.w += acc.w * rs;
    out4[d * 32 + lane] = o;
}

// ---------------- tiled GEMM with FFMA2: BM=128, BK=16, TM=8, TN=8 (4 pairs)
#define BM 128
#define BN 128
#define BK 16
#define TM 8
#define TN 8

template <int MODE>
__global__ __launch_bounds__(256, 2)
void gemm128_kernel(const float* __restrict__ A,
                    const float* __restrict__ B,
                    const float* __restrict__ aux,   // att_src (M0) / bias (M1)
                    float* __restrict__ C,
                    float* __restrict__ alpha_out,
                    int nrows) {
    __shared__ float As[2][BK][BM];
    __shared__ __align__(16) float Bs[2][BK][BN];
    __shared__ float xtra[MODE == 0 ? FDIM : FDIM * HEADS];

    int tid = threadIdx.x;
    int tn_idx = tid & 15;
    int tm_idx = tid >> 4;
    int tm0 = tm_idx * TM;
    int tn0 = tn_idx * TN;
    int m0 = blockIdx.x * BM;

    if (MODE == 0) {
        if (tid < FDIM) xtra[tid] = aux[tid];
    } else {
        xtra[tid] = g_fold_v[tid];
        xtra[tid + 256] = g_fold_v[tid + 256];
    }

    // packed accumulators: acc2[i][j] holds columns (2j, 2j+1) of row i
    u64 acc2[TM][TN / 2];
    #pragma unroll
    for (int i = 0; i < TM; i++)
        #pragma unroll
        for (int j = 0; j < TN / 2; j++) acc2[i][j] = 0ull;

    int af_row[2], af_k4[2];
    int bf_k[2], bf_n4[2];
    #pragma unroll
    for (int i = 0; i < 2; i++) {
        int f = tid + i * 256;
        af_row[i] = f >> 2;
        af_k4[i]  = (f & 3) * 4;
        bf_k[i]   = f >> 5;
        bf_n4[i]  = (f & 31) * 4;
    }

    float4 a_reg[2], b_reg[2];
    const float4 zero4 = make_float4(0.f, 0.f, 0.f, 0.f);

    #pragma unroll
    for (int i = 0; i < 2; i++) {
        int grow = m0 + af_row[i];
        a_reg[i] = (grow < nrows)
            ? *(const float4*)(A + (size_t)grow * FDIM + af_k4[i]) : zero4;
        b_reg[i] = *(const float4*)(B + (size_t)bf_k[i] * FDIM + bf_n4[i]);
    }
    #pragma unroll
    for (int i = 0; i < 2; i++) {
        As[0][af_k4[i] + 0][af_row[i]] = a_reg[i].x;
        As[0][af_k4[i] + 1][af_row[i]] = a_reg[i].y;
        As[0][af_k4[i] + 2][af_row[i]] = a_reg[i].z;
        As[0][af_k4[i] + 3][af_row[i]] = a_reg[i].w;
        *(float4*)&Bs[0][bf_k[i]][bf_n4[i]] = b_reg[i];
    }
    __syncthreads();

    int h  = tn_idx >> 2;
    int qq = (tn_idx & 3) * 2;
    float av0 = 0.f, av1 = 0.f;

    int buf = 0;
    const int NT = FDIM / BK;  // 8 tiles
    for (int t = 0; t < NT; t++) {
        if (t + 1 < NT) {
            int kt = (t + 1) * BK;
            #pragma unroll
            for (int i = 0; i < 2; i++) {
                int grow = m0 + af_row[i];
                a_reg[i] = (grow < nrows)
                    ? *(const float4*)(A + (size_t)grow * FDIM + kt + af_k4[i]) : zero4;
                b_reg[i] = *(const float4*)(B + (size_t)(kt + bf_k[i]) * FDIM + bf_n4[i]);
            }
        }

        #pragma unroll
        for (int k = 0; k < BK; k++) {
            float4 a0 = *(const float4*)&As[buf][k][tm0];
            float4 a1 = *(const float4*)&As[buf][k][tm0 + 4];
            // b pairs: 16B-aligned (tn0 multiple of 8 floats)
            ulonglong2 bq0 = *(const ulonglong2*)&Bs[buf][k][tn0];
            ulonglong2 bq1 = *(const ulonglong2*)&Bs[buf][k][tn0 + 4];
            u64 bp[4] = {bq0.x, bq0.y, bq1.x, bq1.y};
            float avv[TM] = {a0.x, a0.y, a0.z, a0.w, a1.x, a1.y, a1.z, a1.w};
            #pragma unroll
            for (int i = 0; i < TM; i++) {
                u64 ad;
                PACK_DUP_F32X2(ad, avv[i]);
                #pragma unroll
                for (int j = 0; j < TN / 2; j++)
                    FMA_F32X2(acc2[i][j], ad, bp[j], acc2[i][j]);
            }
            if (MODE == 1) {
                float vv = xtra[(t * BK + k) * HEADS + h];
                av0 += As[buf][k][tm0 + qq]     * vv;
                av1 += As[buf][k][tm0 + qq + 1] * vv;
            }
        }

        if (t + 1 < NT) {
            int nb = buf ^ 1;
            #pragma unroll
            for (int i = 0; i < 2; i++) {
                As[nb][af_k4[i] + 0][af_row[i]] = a_reg[i].x;
                As[nb][af_k4[i] + 1][af_row[i]] = a_reg[i].y;
                As[nb][af_k4[i] + 2][af_row[i]] = a_reg[i].z;
                As[nb][af_k4[i] + 3][af_row[i]] = a_reg[i].w;
                *(float4*)&Bs[nb][bf_k[i]][bf_n4[i]] = b_reg[i];
            }
            __syncthreads();
            buf = nb;
        }
    }

    // unpack accumulators
    float acc[TM][TN];
    #pragma unroll
    for (int i = 0; i < TM; i++)
        #pragma unroll
        for (int j = 0; j < TN / 2; j++) {
            unsigned lo, hi;
            UNPACK_F32X2(lo, hi, acc2[i][j]);
            acc[i][2 * j]     = __uint_as_float(lo);
            acc[i][2 * j + 1] = __uint_as_float(hi);
        }

    float4 bb0 = zero4, bb1 = zero4;
    if (MODE == 1) {
        bb0 = *(const float4*)(aux + tn0);
        bb1 = *(const float4*)(aux + tn0 + 4);
    }
    #pragma unroll
    for (int i = 0; i < TM; i++) {
        int row = m0 + tm0 + i;
        if (row < nrows) {
            float4 o0 = make_float4(acc[i][0] + bb0.x, acc[i][1] + bb0.y,
                                    acc[i][2] + bb0.z, acc[i][3] + bb0.w);
            float4 o1 = make_float4(acc[i][4] + bb1.x, acc[i][5] + bb1.y,
                                    acc[i][6] + bb1.z, acc[i][7] + bb1.w);
            *(float4*)(C + (size_t)row * FDIM + tn0)     = o0;
            *(float4*)(C + (size_t)row * FDIM + tn0 + 4) = o1;
        }
    }

    if (MODE == 0) {
        float a_att[TN];
        #pragma unroll
        for (int j = 0; j < TN; j++) a_att[j] = xtra[tn0 + j];
        #pragma unroll
        for (int i = 0; i < TM; i++) {
            float p = 0.f;
            #pragma unroll
            for (int j = 0; j < TN; j++) p += acc[i][j] * a_att[j];
            p += __shfl_xor_sync(0xffffffffu, p, 1);
            p += __shfl_xor_sync(0xffffffffu, p, 2);
            if ((tn_idx & 3) == 0) {
                int row = m0 + tm0 + i;
                if (row < nrows) alpha_out[row * HEADS + h] = p;
            }
        }
    } else {
        int r0 = m0 + tm0 + qq;
        if (r0 < nrows)     alpha_out[r0 * HEADS + h]       = av0;
        if (r0 + 1 < nrows) alpha_out[(r0 + 1) * HEADS + h] = av1;
    }
}

// ---------------------------------------------------------------------------
extern "C" void kernel_launch(void* const* d_in, const int* in_sizes, int n_in,
                              void* d_out, int out_size) {
    const float* x_src    = (const float*)d_in[0];
    const float* x_dst    = (const float*)d_in[1];
    const int*   edge_src = (const int*)d_in[2];
    const int*   edge_dst = (const int*)d_in[3];
    int off = (n_in >= 11) ? 5 : 4;
    const float* W_src   = (const float*)d_in[off + 0];
    const float* W_dst   = (const float*)d_in[off + 1];
    const float* att_src = (const float*)d_in[off + 2];
    const float* att_dst = (const float*)d_in[off + 3];
    const float* W_self  = (const float*)d_in[off + 4];
    const float* b_self  = (const float*)d_in[off + 5];
    float* out = (float*)d_out;

    int n_src = in_sizes[0] / FDIM;
    int n_dst = in_sizes[1] / FDIM;
    int E     = in_sizes[2];

    static float* p_feat = nullptr;
    static float* p_asrc = nullptr;
    static float* p_adst = nullptr;
    if (!p_feat) {
        cudaGetSymbolAddress((void**)&p_feat, g_feat);
        cudaGetSymbolAddress((void**)&p_asrc, g_asrc);
        cudaGetSymbolAddress((void**)&p_adst, g_adst);
    }

    int nb = (n_dst + SCAN_TILE - 1) / SCAN_TILE;

    // 1) fold for alpha_dst
    fold_kernel<<<1, 128>>>(W_dst, att_dst);

    // 2) CSR skeleton: hist + 3-phase scan + permute scatter (edge-only deps)
    zero_deg_kernel<<<(n_dst + 255) / 256, 256>>>(n_dst);
    hist_kernel<<<(E + 255) / 256, 256>>>(edge_dst, E);
    scan_local_kernel<<<nb, 256>>>(n_dst);
    scan_bsum_kernel<<<1, 256>>>(nb, n_dst);
    scan_apply_kernel<<<nb, 256>>>(n_dst);
    scatter_kernel<<<(E + 255) / 256, 256>>>(edge_src, edge_dst, E);

    // 3) fused GEMMs (FFMA2)
    gemm128_kernel<0><<<(n_src + BM - 1) / BM, 256>>>(
        x_src, W_src, att_src, p_feat, p_asrc, n_src);
    gemm128_kernel<1><<<(n_dst + BM - 1) / BM, 256>>>(
        x_dst, W_self, b_self, out, p_adst, n_dst);

    // 4) gather-aggregate: warp per dst, weights inline, no atomics
    long long total_threads = (long long)n_dst * 32;
    int blocks = (int)((total_threads + 255) / 256);
    aggr_kernel<<<blocks, 256>>>(out, n_dst);
}

// round 8
// speedup vs baseline: 1.7698x; 1.2044x over previous
#include <cuda_runtime.h>
#include <cuda_bf16.h>

// ---------------------------------------------------------------------------
// BipartiteGATConv — round 8: identical kernels to round 7 (all verified),
// launcher restructured with capture-legal stream fork/join so the CSR build
// chain and the two GEMMs run CONCURRENTLY in the captured graph.
//   main: fold -> [fork] gemm0            -> [join] aggr
//   s1:              gemm1
//   s2:              zero,hist,scan,scatter
// ---------------------------------------------------------------------------

#define MAX_N   50000
#define MAX_E   800000
#define FDIM    128
#define HEADS   4
#define SCAN_TILE 1024
#define MAX_SB  ((MAX_N + SCAN_TILE - 1) / SCAN_TILE)

__device__ __align__(16) float g_feat[MAX_N * FDIM];
__device__ __align__(16) float g_asrc[MAX_N * HEADS];
__device__ __align__(16) float g_adst[MAX_N * HEADS];
__device__ __align__(16) float g_fold_v[FDIM * HEADS];
__device__ __align__(16) int   g_deg[MAX_N];
__device__ int   g_row[MAX_N + 1];
__device__ int   g_cursor[MAX_N];
__device__ int   g_bsum[MAX_SB];
__device__ int   g_boff[MAX_SB];
__device__ int   g_csr_s[MAX_E];

typedef unsigned long long u64;

__device__ __forceinline__ float leaky02(float z) {
    return z > 0.f ? z : 0.2f * z;
}

#define FMA_F32X2(d, a, b, c) \
    asm("fma.rn.f32x2 %0, %1, %2, %3;" : "=l"(d) : "l"(a), "l"(b), "l"(c))
#define PACK_DUP_F32X2(d, s) \
    asm("mov.b64 %0, {%1, %1};" : "=l"(d) : "r"(__float_as_uint(s)))
#define UNPACK_F32X2(lo, hi, in) \
    asm("mov.b64 {%0, %1}, %2;" : "=r"(lo), "=r"(hi) : "l"(in))

// ---------------- fold
__global__ void fold_kernel(const float* __restrict__ W_dst,
                            const float* __restrict__ att_dst) {
    int k = threadIdx.x;
    #pragma unroll
    for (int h = 0; h < HEADS; h++) {
        float s = 0.f;
        #pragma unroll 8
        for (int d = 0; d < 32; d++)
            s += W_dst[k * FDIM + h * 32 + d] * att_dst[h * 32 + d];
        g_fold_v[k * HEADS + h] = s;
    }
}

// ---------------- CSR build ----------------
__global__ void zero_deg_kernel(int n) {
    int i = blockIdx.x * blockDim.x + threadIdx.x;
    if (i < n) g_deg[i] = 0;
}

__global__ void hist_kernel(const int* __restrict__ ed, int E) {
    int e = blockIdx.x * blockDim.x + threadIdx.x;
    if (e < E) atomicAdd(&g_deg[ed[e]], 1);
}

__global__ __launch_bounds__(256)
void scan_local_kernel(int n) {
    __shared__ int warp_tot[8];
    int t = threadIdx.x;
    int lane = t & 31, w = t >> 5;
    int base = blockIdx.x * SCAN_TILE + t * 4;

    int4 v = make_int4(0, 0, 0, 0);
    if (base + 3 < n) {
        v = *(const int4*)(g_deg + base);
    } else if (base < n) {
        v.x = g_deg[base];
        if (base + 1 < n) v.y = g_deg[base + 1];
        if (base + 2 < n) v.z = g_deg[base + 2];
    }
    int tot = v.x + v.y + v.z + v.w;

    int inc = tot;
    #pragma unroll
    for (int off = 1; off < 32; off <<= 1) {
        int x = __shfl_up_sync(0xffffffffu, inc, off);
        if (lane >= off) inc += x;
    }
    if (lane == 31) warp_tot[w] = inc;
    __syncthreads();
    if (t < 8) {
        int x = warp_tot[t];
        #pragma unroll
        for (int off = 1; off < 8; off <<= 1) {
            int y = __shfl_up_sync(0xffu, x, off);
            if (t >= off) x += y;
        }
        warp_tot[t] = x;
    }
    __syncthreads();

    int excl = (w > 0 ? warp_tot[w - 1] : 0) + (inc - tot);
    if (base < n) {
        g_row[base] = excl;
        if (base + 1 < n) g_row[base + 1] = excl + v.x;
        if (base + 2 < n) g_row[base + 2] = excl + v.x + v.y;
        if (base + 3 < n) g_row[base + 3] = excl + v.x + v.y + v.z;
    }
    if (t == 0) g_bsum[blockIdx.x] = warp_tot[7];
}

__global__ __launch_bounds__(256)
void scan_bsum_kernel(int nb, int n) {
    __shared__ int s[256];
    int t = threadIdx.x;
    s[t] = (t < nb) ? g_bsum[t] : 0;
    __syncthreads();
    #pragma unroll
    for (int off = 1; off < 256; off <<= 1) {
        int v = (t >= off) ? s[t - off] : 0;
        __syncthreads();
        s[t] += v;
        __syncthreads();
    }
    if (t < nb) g_boff[t] = (t > 0) ? s[t - 1] : 0;
    if (t == 0) g_row[n] = s[255];
}

__global__ __launch_bounds__(256)
void scan_apply_kernel(int n) {
    int t = threadIdx.x;
    int base = blockIdx.x * SCAN_TILE + t * 4;
    int off = g_boff[blockIdx.x];
    #pragma unroll
    for (int j = 0; j < 4; j++) {
        int i = base + j;
        if (i < n) {
            int r = g_row[i] + off;
            g_row[i] = r;
            g_cursor[i] = r;
        }
    }
}

__global__ void scatter_kernel(const int* __restrict__ es,
                               const int* __restrict__ ed, int E) {
    int e = blockIdx.x * blockDim.x + threadIdx.x;
    if (e >= E) return;
    int pos = atomicAdd(&g_cursor[ed[e]], 1);
    g_csr_s[pos] = es[e];
}

// ---------------- aggregate: one warp per dst; weights computed inline
__global__ __launch_bounds__(256)
void aggr_kernel(float* __restrict__ out, int n_dst) {
    int d = (blockIdx.x * blockDim.x + threadIdx.x) >> 5;
    int lane = threadIdx.x & 31;
    if (d >= n_dst) return;
    int h = lane >> 3;

    int i   = g_row[d];
    int end = g_row[d + 1];
    float adv = g_adst[d * HEADS + h];

    float4 acc = make_float4(0.f, 0.f, 0.f, 0.f);
    float wsum = 0.f;
    const float4* feat4 = (const float4*)g_feat;

    int   s_cur = (i < end) ? g_csr_s[i] : 0;
    float a_cur = (i < end) ? g_asrc[s_cur * HEADS + h] : 0.f;
    for (; i < end; ) {
        int inext = i + 1;
        int   s_nxt = 0;
        float a_nxt = 0.f;
        if (inext < end) {
            s_nxt = g_csr_s[inext];
            a_nxt = g_asrc[s_nxt * HEADS + h];
        }
        float w = __expf(leaky02(a_cur + adv));
        float4 f = feat4[s_cur * 32 + lane];
        acc.x += w * f.x; acc.y += w * f.y;
        acc.z += w * f.z; acc.w += w * f.w;
        wsum += w;
        s_cur = s_nxt; a_cur = a_nxt;
        i = inext;
    }

    float rs = 1.f / (wsum + 1e-16f);
    float4* out4 = (float4*)out;
    float4 o = out4[d * 32 + lane];
    o.x += acc.x * rs; o.y += acc.y * rs;
    o.z += acc.z * rs; o.w += acc.w * rs;
    out4[d * 32 + lane] = o;
}

// ---------------- tiled GEMM with FFMA2
#define BM 128
#define BN 128
#define BK 16
#define TM 8
#define TN 8

template <int MODE>
__global__ __launch_bounds__(256, 2)
void gemm128_kernel(const float* __restrict__ A,
                    const float* __restrict__ B,
                    const float* __restrict__ aux,
                    float* __restrict__ C,
                    float* __restrict__ alpha_out,
                    int nrows) {
    __shared__ float As[2][BK][BM];
    __shared__ __align__(16) float Bs[2][BK][BN];
    __shared__ float xtra[MODE == 0 ? FDIM : FDIM * HEADS];

    int tid = threadIdx.x;
    int tn_idx = tid & 15;
    int tm_idx = tid >> 4;
    int tm0 = tm_idx * TM;
    int tn0 = tn_idx * TN;
    int m0 = blockIdx.x * BM;

    if (MODE == 0) {
        if (tid < FDIM) xtra[tid] = aux[tid];
    } else {
        xtra[tid] = g_fold_v[tid];
        xtra[tid + 256] = g_fold_v[tid + 256];
    }

    u64 acc2[TM][TN / 2];
    #pragma unroll
    for (int i = 0; i < TM; i++)
        #pragma unroll
        for (int j = 0; j < TN / 2; j++) acc2[i][j] = 0ull;

    int af_row[2], af_k4[2];
    int bf_k[2], bf_n4[2];
    #pragma unroll
    for (int i = 0; i < 2; i++) {
        int f = tid + i * 256;
        af_row[i] = f >> 2;
        af_k4[i]  = (f & 3) * 4;
        bf_k[i]   = f >> 5;
        bf_n4[i]  = (f & 31) * 4;
    }

    float4 a_reg[2], b_reg[2];
    const float4 zero4 = make_float4(0.f, 0.f, 0.f, 0.f);

    #pragma unroll
    for (int i = 0; i < 2; i++) {
        int grow = m0 + af_row[i];
        a_reg[i] = (grow < nrows)
            ? *(const float4*)(A + (size_t)grow * FDIM + af_k4[i]) : zero4;
        b_reg[i] = *(const float4*)(B + (size_t)bf_k[i] * FDIM + bf_n4[i]);
    }
    #pragma unroll
    for (int i = 0; i < 2; i++) {
        As[0][af_k4[i] + 0][af_row[i]] = a_reg[i].x;
        As[0][af_k4[i] + 1][af_row[i]] = a_reg[i].y;
        As[0][af_k4[i] + 2][af_row[i]] = a_reg[i].z;
        As[0][af_k4[i] + 3][af_row[i]] = a_reg[i].w;
        *(float4*)&Bs[0][bf_k[i]][bf_n4[i]] = b_reg[i];
    }
    __syncthreads();

    int h  = tn_idx >> 2;
    int qq = (tn_idx & 3) * 2;
    float av0 = 0.f, av1 = 0.f;

    int buf = 0;
    const int NT = FDIM / BK;
    for (int t = 0; t < NT; t++) {
        if (t + 1 < NT) {
            int kt = (t + 1) * BK;
            #pragma unroll
            for (int i = 0; i < 2; i++) {
                int grow = m0 + af_row[i];
                a_reg[i] = (grow < nrows)
                    ? *(const float4*)(A + (size_t)grow * FDIM + kt + af_k4[i]) : zero4;
                b_reg[i] = *(const float4*)(B + (size_t)(kt + bf_k[i]) * FDIM + bf_n4[i]);
            }
        }

        #pragma unroll
        for (int k = 0; k < BK; k++) {
            float4 a0 = *(const float4*)&As[buf][k][tm0];
            float4 a1 = *(const float4*)&As[buf][k][tm0 + 4];
            ulonglong2 bq0 = *(const ulonglong2*)&Bs[buf][k][tn0];
            ulonglong2 bq1 = *(const ulonglong2*)&Bs[buf][k][tn0 + 4];
            u64 bp[4] = {bq0.x, bq0.y, bq1.x, bq1.y};
            float avv[TM] = {a0.x, a0.y, a0.z, a0.w, a1.x, a1.y, a1.z, a1.w};
            #pragma unroll
            for (int i = 0; i < TM; i++) {
                u64 ad;
                PACK_DUP_F32X2(ad, avv[i]);
                #pragma unroll
                for (int j = 0; j < TN / 2; j++)
                    FMA_F32X2(acc2[i][j], ad, bp[j], acc2[i][j]);
            }
            if (MODE == 1) {
                float vv = xtra[(t * BK + k) * HEADS + h];
                av0 += As[buf][k][tm0 + qq]     * vv;
                av1 += As[buf][k][tm0 + qq + 1] * vv;
            }
        }

        if (t + 1 < NT) {
            int nb = buf ^ 1;
            #pragma unroll
            for (int i = 0; i < 2; i++) {
                As[nb][af_k4[i] + 0][af_row[i]] = a_reg[i].x;
                As[nb][af_k4[i] + 1][af_row[i]] = a_reg[i].y;
                As[nb][af_k4[i] + 2][af_row[i]] = a_reg[i].z;
                As[nb][af_k4[i] + 3][af_row[i]] = a_reg[i].w;
                *(float4*)&Bs[nb][bf_k[i]][bf_n4[i]] = b_reg[i];
            }
            __syncthreads();
            buf = nb;
        }
    }

    float acc[TM][TN];
    #pragma unroll
    for (int i = 0; i < TM; i++)
        #pragma unroll
        for (int j = 0; j < TN / 2; j++) {
            unsigned lo, hi;
            UNPACK_F32X2(lo, hi, acc2[i][j]);
            acc[i][2 * j]     = __uint_as_float(lo);
            acc[i][2 * j + 1] = __uint_as_float(hi);
        }

    float4 bb0 = zero4, bb1 = zero4;
    if (MODE == 1) {
        bb0 = *(const float4*)(aux + tn0);
        bb1 = *(const float4*)(aux + tn0 + 4);
    }
    #pragma unroll
    for (int i = 0; i < TM; i++) {
        int row = m0 + tm0 + i;
        if (row < nrows) {
            float4 o0 = make_float4(acc[i][0] + bb0.x, acc[i][1] + bb0.y,
                                    acc[i][2] + bb0.z, acc[i][3] + bb0.w);
            float4 o1 = make_float4(acc[i][4] + bb1.x, acc[i][5] + bb1.y,
                                    acc[i][6] + bb1.z, acc[i][7] + bb1.w);
            *(float4*)(C + (size_t)row * FDIM + tn0)     = o0;
            *(float4*)(C + (size_t)row * FDIM + tn0 + 4) = o1;
        }
    }

    if (MODE == 0) {
        float a_att[TN];
        #pragma unroll
        for (int j = 0; j < TN; j++) a_att[j] = xtra[tn0 + j];
        #pragma unroll
        for (int i = 0; i < TM; i++) {
            float p = 0.f;
            #pragma unroll
            for (int j = 0; j < TN; j++) p += acc[i][j] * a_att[j];
            p += __shfl_xor_sync(0xffffffffu, p, 1);
            p += __shfl_xor_sync(0xffffffffu, p, 2);
            if ((tn_idx & 3) == 0) {
                int row = m0 + tm0 + i;
                if (row < nrows) alpha_out[row * HEADS + h] = p;
            }
        }
    } else {
        int r0 = m0 + tm0 + qq;
        if (r0 < nrows)     alpha_out[r0 * HEADS + h]       = av0;
        if (r0 + 1 < nrows) alpha_out[(r0 + 1) * HEADS + h] = av1;
    }
}

// ---------------------------------------------------------------------------
extern "C" void kernel_launch(void* const* d_in, const int* in_sizes, int n_in,
                              void* d_out, int out_size) {
    const float* x_src    = (const float*)d_in[0];
    const float* x_dst    = (const float*)d_in[1];
    const int*   edge_src = (const int*)d_in[2];
    const int*   edge_dst = (const int*)d_in[3];
    int off = (n_in >= 11) ? 5 : 4;
    const float* W_src   = (const float*)d_in[off + 0];
    const float* W_dst   = (const float*)d_in[off + 1];
    const float* att_src = (const float*)d_in[off + 2];
    const float* att_dst = (const float*)d_in[off + 3];
    const float* W_self  = (const float*)d_in[off + 4];
    const float* b_self  = (const float*)d_in[off + 5];
    float* out = (float*)d_out;

    int n_src = in_sizes[0] / FDIM;
    int n_dst = in_sizes[1] / FDIM;
    int E     = in_sizes[2];

    static float* p_feat = nullptr;
    static float* p_asrc = nullptr;
    static float* p_adst = nullptr;
    static cudaStream_t s1 = nullptr, s2 = nullptr;
    static cudaEvent_t ev_fork = nullptr, ev_g1 = nullptr, ev_csr = nullptr;
    if (!p_feat) {
        cudaGetSymbolAddress((void**)&p_feat, g_feat);
        cudaGetSymbolAddress((void**)&p_asrc, g_asrc);
        cudaGetSymbolAddress((void**)&p_adst, g_adst);
        cudaStreamCreateWithFlags(&s1, cudaStreamNonBlocking);
        cudaStreamCreateWithFlags(&s2, cudaStreamNonBlocking);
        cudaEventCreateWithFlags(&ev_fork, cudaEventDisableTiming);
        cudaEventCreateWithFlags(&ev_g1,   cudaEventDisableTiming);
        cudaEventCreateWithFlags(&ev_csr,  cudaEventDisableTiming);
    }

    int nb = (n_dst + SCAN_TILE - 1) / SCAN_TILE;

    // main stream: fold (needed by gemm<1>)
    fold_kernel<<<1, 128>>>(W_dst, att_dst);

    // fork s1 (gemm1) and s2 (CSR chain) off the capture origin stream
    cudaEventRecord(ev_fork, 0);
    cudaStreamWaitEvent(s1, ev_fork, 0);
    cudaStreamWaitEvent(s2, ev_fork, 0);

    // s2: CSR build
    zero_deg_kernel<<<(n_dst + 255) / 256, 256, 0, s2>>>(n_dst);
    hist_kernel<<<(E + 255) / 256, 256, 0, s2>>>(edge_dst, E);
    scan_local_kernel<<<nb, 256, 0, s2>>>(n_dst);
    scan_bsum_kernel<<<1, 256, 0, s2>>>(nb, n_dst);
    scan_apply_kernel<<<nb, 256, 0, s2>>>(n_dst);
    scatter_kernel<<<(E + 255) / 256, 256, 0, s2>>>(edge_src, edge_dst, E);
    cudaEventRecord(ev_csr, s2);

    // s1: dst GEMM (out self-term + alpha_dst)
    gemm128_kernel<1><<<(n_dst + BM - 1) / BM, 256, 0, s1>>>(
        x_dst, W_self, b_self, out, p_adst, n_dst);
    cudaEventRecord(ev_g1, s1);

    // main: src GEMM (feat + alpha_src)
    gemm128_kernel<0><<<(n_src + BM - 1) / BM, 256>>>(
        x_src, W_src, att_src, p_feat, p_asrc, n_src);

    // join: aggr needs feat/asrc (main), adst+out (s1), CSR (s2)
    cudaStreamWaitEvent(0, ev_g1, 0);
    cudaStreamWaitEvent(0, ev_csr, 0);
    long long total_threads = (long long)n_dst * 32;
    int blocks = (int)((total_threads + 255) / 256);
    aggr_kernel<<<blocks, 256>>>(out, n_dst);
}